// round 9
// baseline (speedup 1.0000x reference)
#include <cuda_runtime.h>

// B=2048 rows, N=8192 cols. One CTA per row, 1024 threads x 8 elems.
// Per row: r = |y_true - y_pred|; solve mean(sinh(r/eps))=1.
// KEY CHANGE (round 9): the solve runs in MOMENT SPACE. With t=r/rmax,
// x=beta*rmax:  sum_i sinh(beta*r_i) = sum_j x^(2j+1) * m_(2j+1) / (2j+1)!,
// m_k = sum_i t_i^k  (14 odd moments, k=1..27; all terms positive, x<=x0=
// ln(2N)=9.704 since the root lies below the reference init, so the k=29
// tail is ~1e-6 relative). One FMA-only pass builds the moments; Newton on
// h(x)=log(P(x))-log(N) then runs on 14 scalars in warp 0 (8 fixed damped
// iterations, ~zero cost) -- NO per-element exps in the solver at all.
// Same unique root as the reference's 20 eps-space Newton iterations, to
// ~1e-6, far inside the 1e-3 gate. Then eps=rmax/x (floored 1e-8),
// betaF=1/(eps+1e-6) per reference; q=sinh(betaF*r) (2 exps/elem, the only
// per-element MUFU); qmax=sinh(betaF*rmax) analytically (sinh monotone);
// Lambda' = 0.99*Lambda + 0.1*(0.9*q/(qmax+1e-20) + 0.1);
// loss = mean((Lambda'*r)^2) via per-row partials + tiny second kernel.
// Output: d_out[0] = loss, d_out[1..B*N] = Lambda' (row-major).

#define BDIM 1024
#define VPT 8
#define MOM 14   // odd moments k = 1,3,...,27

static constexpr int B = 2048;
static constexpr int N = 8192;
static constexpr float LOG_2N = 9.70406052783923f;   // ln(16384)
static constexpr float LOG_N  = 9.01091334727929f;   // ln(8192)

__device__ float g_row_loss[B];

// 1/(2j+1)! for j=0..13
__device__ __constant__ float INVF[MOM] = {
    1.0f, 1.6666667e-1f, 8.3333333e-3f, 1.9841270e-4f,
    2.7557319e-6f, 2.5052108e-8f, 1.6059044e-10f, 7.6471637e-13f,
    2.8114573e-15f, 8.2206352e-18f, 1.9572941e-20f, 3.8681702e-23f,
    6.4469503e-26f, 9.1836899e-29f};

__device__ __forceinline__ float warp_sum(float v) {
#pragma unroll
    for (int o = 16; o; o >>= 1) v += __shfl_xor_sync(0xffffffffu, v, o);
    return v;
}
__device__ __forceinline__ float warp_max(float v) {
#pragma unroll
    for (int o = 16; o; o >>= 1) v = fmaxf(v, __shfl_xor_sync(0xffffffffu, v, o));
    return v;
}

__global__ __launch_bounds__(BDIM)
void custom_loss_row_kernel(const float* __restrict__ y_pred,
                            const float* __restrict__ y_true,
                            const float* __restrict__ Lam,
                            float* __restrict__ out_lambda) {
    const int b = blockIdx.x;
    const size_t base = (size_t)b * N;
    const int t = threadIdx.x;
    const int lane = t & 31;
    const int wid = t >> 5;

    __shared__ float sA[32];          // rmax partials, later loss partials
    __shared__ float sm_m[32][MOM];   // per-warp moment partials
    __shared__ float sm_f[MOM];       // final moments
    __shared__ float sc[2];           // betaF, inv_qm

    // ---- residuals: float4 loads, 8 elems/thread ----
    const float4* yp4 = (const float4*)(y_pred + base);
    const float4* yt4 = (const float4*)(y_true + base);
    float r[VPT];
    {
        const float4 p0 = yp4[t], g0 = yt4[t];
        r[0] = fabsf(g0.x - p0.x); r[1] = fabsf(g0.y - p0.y);
        r[2] = fabsf(g0.z - p0.z); r[3] = fabsf(g0.w - p0.w);
        const float4 p1 = yp4[t + BDIM], g1 = yt4[t + BDIM];
        r[4] = fabsf(g1.x - p1.x); r[5] = fabsf(g1.y - p1.y);
        r[6] = fabsf(g1.z - p1.z); r[7] = fabsf(g1.w - p1.w);
    }

    // ---- barrier 1: row max(r) ----
    float m = r[0];
#pragma unroll
    for (int i = 1; i < VPT; i++) m = fmaxf(m, r[i]);
    m = warp_max(m);
    if (lane == 0) sA[wid] = m;
    __syncthreads();
    const float rmax = warp_max(sA[lane]);  // uniform across block
    const float inv_rmax = __fdividef(1.0f, fmaxf(rmax, 1e-30f));

    // ---- moment pass: 14 odd power sums of t = r/rmax (FMA only) ----
    float mom[MOM];
#pragma unroll
    for (int j = 0; j < MOM; j++) mom[j] = 0.0f;
#pragma unroll
    for (int i = 0; i < VPT; i++) {
        const float tv = r[i] * inv_rmax;
        const float t2 = tv * tv;
        float p = tv;
        mom[0] += p;
#pragma unroll
        for (int j = 1; j < MOM; j++) { p *= t2; mom[j] += p; }
    }
#pragma unroll
    for (int j = 0; j < MOM; j++) mom[j] = warp_sum(mom[j]);
    if (lane == 0) {
#pragma unroll
        for (int j = 0; j < MOM; j++) sm_m[wid][j] = mom[j];
    }

    // Pre-issue Lambda loads: consumed only after the solve, so the DRAM
    // latency overlaps the moment reduce + scalar Newton.
    const float4* L4 = (const float4*)(Lam + base);
    const float4 l0 = L4[t];
    const float4 l1 = L4[t + BDIM];

    __syncthreads();  // barrier 2: moment partials visible

    // ---- cross-warp moment reduce: warp j (j<14, FULL warps) sums moment j
    if (wid < MOM) {
        const float v = warp_sum(sm_m[lane][wid]);
        if (lane == 0) sm_f[wid] = v;
    }
    __syncthreads();  // barrier 3: final moments visible

    // ---- scalar Newton in warp 0 only (redundant across its 32 lanes) ----
    // P(x) = sum_j a_j x^(2j+1), a_j = m_j/(2j+1)!;  Q = dP/dx.
    // h(x) = log P - log N; 8 damped iterations; x clamped <= x0 keeps the
    // truncated series valid (tail ~1e-6 relative at x0=9.704).
    if (wid == 0) {
        float a[MOM], bq[MOM];
#pragma unroll
        for (int j = 0; j < MOM; j++) {
            a[j]  = sm_f[j] * INVF[j];
            bq[j] = (float)(2 * j + 1) * a[j];
        }
        const float beta0 = (LOG_2N + 1e-8f) / fmaxf(rmax, 1e-8f);
        const float x0 = beta0 * rmax;
        float x = x0;
#pragma unroll 1
        for (int itn = 0; itn < 8; itn++) {
            const float y = x * x;
            float P = a[MOM - 1], Q = bq[MOM - 1];
#pragma unroll
            for (int j = MOM - 2; j >= 0; j--) {
                P = fmaf(P, y, a[j]);
                Q = fmaf(Q, y, bq[j]);
            }
            P *= x;  // P(x); Q = P'(x)
            const float h  = __logf(P) - LOG_N;
            const float dx = h * __fdividef(P, Q);
            const float xn = x - dx;
            x = fminf(fminf(fmaxf(xn, 0.5f * x), 1.5f * x), x0);
        }
        // final beta exactly as reference: eps floor, then +1e-6
        const float eps = fmaxf(__fdividef(rmax, x), 1e-8f);
        const float betaF = __fdividef(1.0f, eps + 1e-6f);
        const float xF = betaF * rmax;
        const float qmax = 0.5f * (__expf(xF) - __expf(-xF));
        if (lane == 0) {
            sc[0] = betaF;
            sc[1] = __fdividef(1.0f, qmax + 1e-20f);
        }
    }
    __syncthreads();  // barrier 4: betaF / inv_qm visible
    const float betaF = sc[0];
    const float inv_qm = sc[1];

    // ---- q = sinh(betaF*r) (only per-element exps in the kernel),
    //      Lambda update, per-row loss partial ----
    // (scalar stores: out base is +1 float, so 16B-misaligned)
    float lsum = 0.0f;
    {
        const float la0[4] = {l0.x, l0.y, l0.z, l0.w};
#pragma unroll
        for (int i = 0; i < 4; i++) {
            const float x  = betaF * r[i];
            const float q  = 0.5f * (__expf(x) - __expf(-x));
            const float qn = q * inv_qm;
            const float lam = fmaf(0.99f, la0[i], 0.1f * fmaf(0.9f, qn, 0.1f));
            out_lambda[base + 4 * t + i] = lam;
            const float z = lam * r[i];
            lsum = fmaf(z, z, lsum);
        }
        const float la1[4] = {l1.x, l1.y, l1.z, l1.w};
#pragma unroll
        for (int i = 0; i < 4; i++) {
            const float x  = betaF * r[4 + i];
            const float q  = 0.5f * (__expf(x) - __expf(-x));
            const float qn = q * inv_qm;
            const float lam = fmaf(0.99f, la1[i], 0.1f * fmaf(0.9f, qn, 0.1f));
            out_lambda[base + 4 * (t + BDIM) + i] = lam;
            const float z = lam * r[4 + i];
            lsum = fmaf(z, z, lsum);
        }
    }
    lsum = warp_sum(lsum);
    if (lane == 0) sA[wid] = lsum;   // sA reads all finished before barrier 2
    __syncthreads();  // barrier 5
    if (t == 0) {
        float v = 0.0f;
#pragma unroll
        for (int i = 0; i < 32; i++) v += sA[i];
        g_row_loss[b] = v;
    }
}

__global__ void loss_reduce_kernel(float* __restrict__ out_loss) {
    const int t = threadIdx.x;  // 1024 threads
    float s = g_row_loss[t] + g_row_loss[t + 1024];
    s = warp_sum(s);
    __shared__ float sm[32];
    if ((t & 31) == 0) sm[t >> 5] = s;
    __syncthreads();
    if (t < 32) {
        float v = warp_sum(sm[t]);
        if (t == 0) out_loss[0] = v * (1.0f / 16777216.0f);  // / (B*N)
    }
}

extern "C" void kernel_launch(void* const* d_in, const int* in_sizes, int n_in,
                              void* d_out, int out_size) {
    const float* y_pred = (const float*)d_in[0];
    const float* y_true = (const float*)d_in[1];
    const float* Lam    = (const float*)d_in[2];
    // d_in[3] = it (unused by the cosh branch)

    float* out = (float*)d_out;       // out[0] = loss
    float* out_lambda = out + 1;      // out[1..] = updated Lambda

    custom_loss_row_kernel<<<B, BDIM>>>(y_pred, y_true, Lam, out_lambda);
    loss_reduce_kernel<<<1, 1024>>>(out);
}

// round 10
// speedup vs baseline: 1.8728x; 1.8728x over previous
#include <cuda_runtime.h>

// B=2048 rows, N=8192 cols. PERSISTENT kernel: 296 CTAs (2 per SM) x 512
// threads; CTA c processes rows c, c+296, ... (<=7 rows). At the start of
// each row it L2-prefetches the NEXT row's y_pred / y_true / Lambda so the
// DRAM fill overlaps the current row's Newton compute (previously the load
// phase and MUFU phase executed serially -> 84us plateau).
//
// Per row: r = |y_true-y_pred|; Newton in beta=1/eps on
// h(beta)=log(sum sinh(beta*r)) - ln(2N) (same unique root as the
// reference's 20 eps-space Newton iterations, converged far past the 1e-3
// gate): 2 warm-start rounds on log(sum e^{beta r})-ln(2N) (1 exp/elem;
// e^{beta0*rmax}=2N at the reference init, monotone), then full rounds
// (2 exp/elem) with early exit at |db|<1e-5*beta. eps=1/beta (floored),
// betaF=1/(eps+1e-6) per reference; q=sinh(betaF*r); qmax=sinh(betaF*rmax)
// (sinh monotone on r>=0); Lambda'=0.99*Lambda+0.1*(0.9*q/(qmax+1e-20)+0.1);
// loss=mean((Lambda'*r)^2) via per-row partials + tiny second kernel.
// Output: d_out[0]=loss, d_out[1..B*N]=Lambda' (row-major).

#define BDIM 512
#define VPT 16
#define NWARP (BDIM / 32)   // 16
#define NCTA 296            // 2 CTAs per SM x 148 SMs

static constexpr int B = 2048;
static constexpr int N = 8192;
static constexpr float LOG_2N = 9.70406052783923f;  // ln(2*N) = ln(16384)

__device__ float g_row_loss[B];

__device__ __forceinline__ float warp_sum(float v) {
#pragma unroll
    for (int o = 16; o; o >>= 1) v += __shfl_xor_sync(0xffffffffu, v, o);
    return v;
}
__device__ __forceinline__ float warp_max(float v) {
#pragma unroll
    for (int o = 16; o; o >>= 1) v = fmaxf(v, __shfl_xor_sync(0xffffffffu, v, o));
    return v;
}

__global__ __launch_bounds__(BDIM, 2)
void custom_loss_row_kernel(const float* __restrict__ y_pred,
                            const float* __restrict__ y_true,
                            const float* __restrict__ Lam,
                            float* __restrict__ out_lambda) {
    const int t = threadIdx.x;
    const int lane = t & 31;
    const int wid = t >> 5;

    __shared__ float s1s[32];   // 16 warp partials + 16 zero-pad
    __shared__ float s2s[32];
    __shared__ float bcast;
    __shared__ int   sdone;

    // zero-pad slots 16..31 once (neutral for max since r>=0 and for sums;
    // wid<16 so never rewritten). Visible after the first rowmax barrier.
    if (t >= NWARP && t < 32) { s1s[t] = 0.0f; s2s[t] = 0.0f; }

#pragma unroll 1
    for (int row = blockIdx.x; row < B; row += NCTA) {
        const size_t base = (size_t)row * N;

        // ---- residuals: float4 loads (L2 hits when prefetched) ----
        const float4* yp4 = (const float4*)(y_pred + base);
        const float4* yt4 = (const float4*)(y_true + base);
        float r[VPT];
#pragma unroll
        for (int c = 0; c < 4; c++) {
            const float4 p = yp4[t + c * BDIM];
            const float4 g = yt4[t + c * BDIM];
            r[4 * c + 0] = fabsf(g.x - p.x);
            r[4 * c + 1] = fabsf(g.y - p.y);
            r[4 * c + 2] = fabsf(g.z - p.z);
            r[4 * c + 3] = fabsf(g.w - p.w);
        }

        // ---- L2-prefetch the NEXT row (yp/yt/Lam; 256 x 128B lines each;
        //      one line per thread slot, t<256 handles yp+Lam, t>=256 yt).
        //      This DRAM fill overlaps the whole Newton solve below. ----
        {
            const int nrow = row + NCTA;
            if (nrow < B) {
                const size_t nb = (size_t)nrow * N;
                if (t < 256) {
                    asm volatile("prefetch.global.L2 [%0];" ::
                                 "l"(y_pred + nb + (size_t)t * 32));
                    asm volatile("prefetch.global.L2 [%0];" ::
                                 "l"(Lam + nb + (size_t)t * 32));
                } else {
                    asm volatile("prefetch.global.L2 [%0];" ::
                                 "l"(y_true + nb + (size_t)(t - 256) * 32));
                }
            }
        }

        // ---- row max(r) ----
        float m = r[0];
#pragma unroll
        for (int i = 1; i < VPT; i++) m = fmaxf(m, r[i]);
        m = warp_max(m);
        if (lane == 0) s1s[wid] = m;
        __syncthreads();
        if (t < 32) {
            float v = warp_max(s1s[lane]);   // full warp, full-mask shuffles
            if (t == 0) bcast = v;
        }
        __syncthreads();
        const float rmax = bcast;

        // beta0 = 1/eps0, eps0 = max(rmax,1e-8)/(ln(2N)+1e-8)  (ref init)
        float beta = (LOG_2N + 1e-8f) / fmaxf(rmax, 1e-8f);

        // ---- phase 1: 2 warm-start iterations (e^{+x} only) ----
#pragma unroll 1
        for (int itn = 0; itn < 2; itn++) {
            float S = 0.0f, T = 0.0f;
#pragma unroll
            for (int i = 0; i < VPT; i++) {
                const float E = __expf(beta * r[i]);
                S += E;
                T = fmaf(E, r[i], T);
            }
            S = warp_sum(S);
            T = warp_sum(T);
            if (lane == 0) { s1s[wid] = S; s2s[wid] = T; }
            __syncthreads();
            if (t < 32) {
                const float S2 = warp_sum(s1s[lane]);
                const float T2 = warp_sum(s2s[lane]);
                if (t == 0) {
                    const float h  = __logf(S2) - LOG_2N;
                    const float db = h * __fdividef(S2, T2);
                    float nb = beta - db;
                    bcast = fminf(fmaxf(nb, 0.05f * beta), 4.0f * beta);
                }
            }
            __syncthreads();
            beta = bcast;
        }

        // ---- phase 2: full Newton, S=sum(e^x-e^-x), early exit ----
#pragma unroll 1
        for (int itn = 0; itn < 10; itn++) {
            float S = 0.0f, T = 0.0f;
#pragma unroll
            for (int i = 0; i < VPT; i++) {
                const float x  = beta * r[i];
                const float E  = __expf(x);
                const float Em = __expf(-x);
                S += (E - Em);
                T = fmaf(E + Em, r[i], T);
            }
            S = warp_sum(S);
            T = warp_sum(T);
            if (lane == 0) { s1s[wid] = S; s2s[wid] = T; }
            __syncthreads();
            if (t < 32) {
                const float S2 = warp_sum(s1s[lane]);
                const float T2 = warp_sum(s2s[lane]);
                if (t == 0) {
                    const float h  = __logf(S2) - LOG_2N;
                    const float db = h * __fdividef(S2, T2);
                    float nb = beta - db;
                    bcast = fminf(fmaxf(nb, 0.05f * beta), 4.0f * beta);
                    sdone = (fabsf(db) < 1e-5f * beta) ? 1 : 0;
                }
            }
            __syncthreads();
            beta = bcast;
            if (sdone) break;  // uniform across block
        }

        // ---- final beta exactly as reference: eps floor, then +1e-6 ----
        const float eps = fmaxf(__fdividef(1.0f, beta), 1e-8f);
        const float betaF = __fdividef(1.0f, eps + 1e-6f);

        // qmax analytically: sinh monotone on r>=0 -> max at rmax
        const float xm = betaF * rmax;
        const float qmax = 0.5f * (__expf(xm) - __expf(-xm));
        const float inv_qm = __fdividef(1.0f, qmax + 1e-20f);

        // ---- q, Lambda update, per-row loss partial ----
        // (float4 Lambda loads, L2-hit; scalar stores: out base is +1 float)
        const float4* L4 = (const float4*)(Lam + base);
        float lsum = 0.0f;
#pragma unroll
        for (int c = 0; c < 4; c++) {
            const float4 l = L4[t + c * BDIM];
            const float la[4] = {l.x, l.y, l.z, l.w};
#pragma unroll
            for (int i = 0; i < 4; i++) {
                const float rv = r[4 * c + i];
                const float x  = betaF * rv;
                const float q  = 0.5f * (__expf(x) - __expf(-x));
                const float qn = q * inv_qm;
                const float lam = fmaf(0.99f, la[i], 0.1f * fmaf(0.9f, qn, 0.1f));
                out_lambda[base + 4 * (t + c * BDIM) + i] = lam;
                const float z = lam * rv;
                lsum = fmaf(z, z, lsum);
            }
        }
        lsum = warp_sum(lsum);
        __syncthreads();  // prior s1s readers done before reuse
        if (lane == 0) s1s[wid] = lsum;
        __syncthreads();
        if (t == 0) {
            float v = 0.0f;
#pragma unroll
            for (int i = 0; i < NWARP; i++) v += s1s[i];
            g_row_loss[row] = v;
        }
        __syncthreads();  // t==0 read of s1s done before next row's rowmax
    }
}

__global__ void loss_reduce_kernel(float* __restrict__ out_loss) {
    const int t = threadIdx.x;  // 1024 threads
    float s = g_row_loss[t] + g_row_loss[t + 1024];
    s = warp_sum(s);
    __shared__ float sm[32];
    if ((t & 31) == 0) sm[t >> 5] = s;
    __syncthreads();
    if (t < 32) {
        float v = warp_sum(sm[t]);
        if (t == 0) out_loss[0] = v * (1.0f / 16777216.0f);  // / (B*N)
    }
}

extern "C" void kernel_launch(void* const* d_in, const int* in_sizes, int n_in,
                              void* d_out, int out_size) {
    const float* y_pred = (const float*)d_in[0];
    const float* y_true = (const float*)d_in[1];
    const float* Lam    = (const float*)d_in[2];
    // d_in[3] = it (unused by the cosh branch)

    float* out = (float*)d_out;       // out[0] = loss
    float* out_lambda = out + 1;      // out[1..] = updated Lambda

    custom_loss_row_kernel<<<NCTA, BDIM>>>(y_pred, y_true, Lam, out_lambda);
    loss_reduce_kernel<<<1, 1024>>>(out);
}

// round 11
// speedup vs baseline: 2.1392x; 1.1422x over previous
#include <cuda_runtime.h>

// B=2048 rows, N=8192 cols. PERSISTENT kernel: 296 CTAs (2/SM) x 512 thr;
// CTA c handles rows c, c+296, ... with next-row L2 prefetch.
//
// KEY CHANGE (round 11): closed-form statistical init for the solver.
// For half-normal residuals r=|N(0,s)|, E e^{beta r} = 2 e^{(beta s)^2/2}
// Phi(beta s) exactly, so the root of mean(sinh(beta*r))=1 is universal in
// v = beta*s:  e^{v^2/2} Phi(v) = 1 + e^{v^2/2} Phi(-v)/2  =>  v* = 0.8435.
// shat = sqrt(sum r^2 / N) is accumulated for free inside the rowmax round,
// beta_init = v*/shat (clamped to (0, beta0], beta0 = reference init, which
// provably upper-bounds the root since sum sinh(beta0*r) >= sinh(ln 2N) ~ N).
// Finite-N sampling puts the init within ~1% of the root => 1-2 clamped
// Newton polish rounds on h(beta)=log(sum sinh(beta*r))-ln(2N) (same unique
// root as the reference's 20 eps-space Newton iterations; exit |db|<1e-5*beta;
// init quality affects speed only, never correctness - 10-round budget).
// Then eps=1/beta (floored), betaF=1/(eps+1e-6) per reference;
// q=sinh(betaF*r); qmax=sinh(betaF*rmax) (sinh monotone on r>=0);
// Lambda' = 0.99*Lambda + 0.1*(0.9*q/(qmax+1e-20)+0.1);
// loss = mean((Lambda'*r)^2) via per-row partials + tiny second kernel.
// Output: d_out[0]=loss, d_out[1..B*N]=Lambda' (row-major).

#define BDIM 512
#define VPT 16
#define NWARP (BDIM / 32)   // 16
#define NCTA 296            // 2 CTAs per SM x 148 SMs

static constexpr int B = 2048;
static constexpr int N = 8192;
static constexpr float LOG_2N = 9.70406052783923f;  // ln(2*N) = ln(16384)
static constexpr float VSTAR  = 0.8435f;            // universal root of the
// half-normal moment equation e^{v^2/2}Phi(v) = 1 + e^{v^2/2}Phi(-v)/2

__device__ float g_row_loss[B];

__device__ __forceinline__ float warp_sum(float v) {
#pragma unroll
    for (int o = 16; o; o >>= 1) v += __shfl_xor_sync(0xffffffffu, v, o);
    return v;
}
__device__ __forceinline__ float warp_max(float v) {
#pragma unroll
    for (int o = 16; o; o >>= 1) v = fmaxf(v, __shfl_xor_sync(0xffffffffu, v, o));
    return v;
}

__global__ __launch_bounds__(BDIM, 2)
void custom_loss_row_kernel(const float* __restrict__ y_pred,
                            const float* __restrict__ y_true,
                            const float* __restrict__ Lam,
                            float* __restrict__ out_lambda) {
    const int t = threadIdx.x;
    const int lane = t & 31;
    const int wid = t >> 5;

    __shared__ float s1s[32];   // 16 warp partials + 16 zero-pad
    __shared__ float s2s[32];
    __shared__ float bc_max;
    __shared__ float bc_ss;
    __shared__ float bcast;
    __shared__ int   sdone;

    // zero-pad slots 16..31 once (neutral for max since r>=0 and for sums;
    // wid<16 so never rewritten). Visible after the first barrier.
    if (t >= NWARP && t < 32) { s1s[t] = 0.0f; s2s[t] = 0.0f; }

#pragma unroll 1
    for (int row = blockIdx.x; row < B; row += NCTA) {
        const size_t base = (size_t)row * N;

        // ---- residuals: float4 loads (L2 hits when prefetched) ----
        const float4* yp4 = (const float4*)(y_pred + base);
        const float4* yt4 = (const float4*)(y_true + base);
        float r[VPT];
#pragma unroll
        for (int c = 0; c < 4; c++) {
            const float4 p = yp4[t + c * BDIM];
            const float4 g = yt4[t + c * BDIM];
            r[4 * c + 0] = fabsf(g.x - p.x);
            r[4 * c + 1] = fabsf(g.y - p.y);
            r[4 * c + 2] = fabsf(g.z - p.z);
            r[4 * c + 3] = fabsf(g.w - p.w);
        }

        // ---- L2-prefetch the NEXT row (yp/yt/Lam; one 128B line per slot)
        {
            const int nrow = row + NCTA;
            if (nrow < B) {
                const size_t nb = (size_t)nrow * N;
                if (t < 256) {
                    asm volatile("prefetch.global.L2 [%0];" ::
                                 "l"(y_pred + nb + (size_t)t * 32));
                    asm volatile("prefetch.global.L2 [%0];" ::
                                 "l"(Lam + nb + (size_t)t * 32));
                } else {
                    asm volatile("prefetch.global.L2 [%0];" ::
                                 "l"(y_true + nb + (size_t)(t - 256) * 32));
                }
            }
        }

        // ---- round 1: row max(r) AND sum(r^2) in one barrier round ----
        float m = r[0];
        float ss = r[0] * r[0];
#pragma unroll
        for (int i = 1; i < VPT; i++) {
            m = fmaxf(m, r[i]);
            ss = fmaf(r[i], r[i], ss);
        }
        m = warp_max(m);
        ss = warp_sum(ss);
        if (lane == 0) { s1s[wid] = m; s2s[wid] = ss; }
        __syncthreads();
        if (t < 32) {
            const float vm = warp_max(s1s[lane]);  // full warp, full-mask
            const float vs = warp_sum(s2s[lane]);
            if (t == 0) { bc_max = vm; bc_ss = vs; }
        }
        __syncthreads();
        const float rmax = bc_max;
        const float sumsq = bc_ss;

        // beta0 = reference init = (ln(2N)+1e-8)/max(rmax,1e-8); root <= beta0.
        const float beta0 = (LOG_2N + 1e-8f) / fmaxf(rmax, 1e-8f);
        // statistical init: shat = sqrt(sumsq/N); beta = v*/shat, clamped.
        const float shat = sqrtf(sumsq * (1.0f / (float)N)) + 1e-30f;
        float beta = fminf(__fdividef(VSTAR, shat), beta0);

        // ---- polish: clamped Newton on h(beta)=log(S)-ln(2N),
        //      S = sum(e^x - e^-x); early exit at |db| < 1e-5*beta ----
#pragma unroll 1
        for (int itn = 0; itn < 10; itn++) {
            float S = 0.0f, T = 0.0f;
#pragma unroll
            for (int i = 0; i < VPT; i++) {
                const float x  = beta * r[i];
                const float E  = __expf(x);
                const float Em = __expf(-x);
                S += (E - Em);
                T = fmaf(E + Em, r[i], T);
            }
            S = warp_sum(S);
            T = warp_sum(T);
            if (lane == 0) { s1s[wid] = S; s2s[wid] = T; }
            __syncthreads();
            if (t < 32) {
                const float S2 = warp_sum(s1s[lane]);
                const float T2 = warp_sum(s2s[lane]);
                if (t == 0) {
                    const float h  = __logf(S2) - LOG_2N;
                    const float db = h * __fdividef(S2, T2);
                    float nb = beta - db;
                    bcast = fminf(fmaxf(nb, 0.05f * beta), 4.0f * beta);
                    sdone = (fabsf(db) < 1e-5f * beta) ? 1 : 0;
                }
            }
            __syncthreads();
            beta = bcast;
            if (sdone) break;  // uniform across block
        }

        // ---- final beta exactly as reference: eps floor, then +1e-6 ----
        const float eps = fmaxf(__fdividef(1.0f, beta), 1e-8f);
        const float betaF = __fdividef(1.0f, eps + 1e-6f);

        // qmax analytically: sinh monotone on r>=0 -> max at rmax
        const float xm = betaF * rmax;
        const float qmax = 0.5f * (__expf(xm) - __expf(-xm));
        const float inv_qm = __fdividef(1.0f, qmax + 1e-20f);

        // ---- q, Lambda update, per-row loss partial ----
        // (float4 Lambda loads, L2-hit; scalar stores: out base is +1 float)
        const float4* L4 = (const float4*)(Lam + base);
        float lsum = 0.0f;
#pragma unroll
        for (int c = 0; c < 4; c++) {
            const float4 l = L4[t + c * BDIM];
            const float la[4] = {l.x, l.y, l.z, l.w};
#pragma unroll
            for (int i = 0; i < 4; i++) {
                const float rv = r[4 * c + i];
                const float x  = betaF * rv;
                const float q  = 0.5f * (__expf(x) - __expf(-x));
                const float qn = q * inv_qm;
                const float lam = fmaf(0.99f, la[i], 0.1f * fmaf(0.9f, qn, 0.1f));
                out_lambda[base + 4 * (t + c * BDIM) + i] = lam;
                const float z = lam * rv;
                lsum = fmaf(z, z, lsum);
            }
        }
        lsum = warp_sum(lsum);
        __syncthreads();  // prior s1s readers done before reuse
        if (lane == 0) s1s[wid] = lsum;
        __syncthreads();
        if (t == 0) {
            float v = 0.0f;
#pragma unroll
            for (int i = 0; i < NWARP; i++) v += s1s[i];
            g_row_loss[row] = v;
        }
        __syncthreads();  // t==0 read of s1s done before next row's round 1
    }
}

__global__ void loss_reduce_kernel(float* __restrict__ out_loss) {
    const int t = threadIdx.x;  // 1024 threads
    float s = g_row_loss[t] + g_row_loss[t + 1024];
    s = warp_sum(s);
    __shared__ float sm[32];
    if ((t & 31) == 0) sm[t >> 5] = s;
    __syncthreads();
    if (t < 32) {
        float v = warp_sum(sm[t]);
        if (t == 0) out_loss[0] = v * (1.0f / 16777216.0f);  // / (B*N)
    }
}

extern "C" void kernel_launch(void* const* d_in, const int* in_sizes, int n_in,
                              void* d_out, int out_size) {
    const float* y_pred = (const float*)d_in[0];
    const float* y_true = (const float*)d_in[1];
    const float* Lam    = (const float*)d_in[2];
    // d_in[3] = it (unused by the cosh branch)

    float* out = (float*)d_out;       // out[0] = loss
    float* out_lambda = out + 1;      // out[1..] = updated Lambda

    custom_loss_row_kernel<<<NCTA, BDIM>>>(y_pred, y_true, Lam, out_lambda);
    loss_reduce_kernel<<<1, 1024>>>(out);
}

// round 12
// speedup vs baseline: 2.1590x; 1.0093x over previous
#include <cuda_runtime.h>

// B=2048 rows, N=8192 cols. PERSISTENT kernel: 296 CTAs (2/SM) x 512 thr;
// CTA c handles rows c, c+296, ... with next-row L2 prefetch.
//
// Solver: closed-form statistical init + clamped Newton polish.
// For half-normal residuals r=|N(0,s)|, the root of mean(sinh(beta*r))=1 is
// universal in v=beta*s: v* = 0.8435. shat=sqrt(sum r^2/N) (accumulated for
// free in the rowmax round) gives beta_init = v*/shat, clamped to (0,beta0]
// (beta0 = reference init, a proven upper bound of the root). Clamped Newton
// on h(beta)=log(sum sinh(beta*r))-ln(2N) (same unique root as the
// reference's 20 eps-space Newton iterations). Exit at |db|<3e-4*beta: db is
// APPLIED before exit, so quadratic convergence leaves ~1e-8 error; the
// threshold only gates the next round => typically 2 polish rounds.
// Then eps=1/beta (floored), betaF=1/(eps+1e-6) per reference;
// q=sinh(betaF*r); qmax=sinh(betaF*rmax) (sinh monotone on r>=0);
// Lambda' = 0.99*Lambda + 0.1*(0.9*q/(qmax+1e-20)+0.1);
// loss = mean((Lambda'*r)^2), fused: per-row partials in g_row_loss, the
// LAST CTA to finish (once-per-CTA fence+counter, off the row hot path)
// reduces all 2048 partials in fixed order and writes d_out[0]; the counter
// self-resets so every graph replay behaves identically.
// Output: d_out[0]=loss, d_out[1..B*N]=Lambda' (row-major).

#define BDIM 512
#define VPT 16
#define NWARP (BDIM / 32)   // 16
#define NCTA 296            // 2 CTAs per SM x 148 SMs

static constexpr int B = 2048;
static constexpr int N = 8192;
static constexpr float LOG_2N = 9.70406052783923f;  // ln(2*N) = ln(16384)
static constexpr float VSTAR  = 0.8435f;            // universal root of the
// half-normal moment equation e^{v^2/2}Phi(v) = 1 + e^{v^2/2}Phi(-v)/2

__device__ float g_row_loss[B];
__device__ unsigned int g_count = 0;

__device__ __forceinline__ float warp_sum(float v) {
#pragma unroll
    for (int o = 16; o; o >>= 1) v += __shfl_xor_sync(0xffffffffu, v, o);
    return v;
}
__device__ __forceinline__ float warp_max(float v) {
#pragma unroll
    for (int o = 16; o; o >>= 1) v = fmaxf(v, __shfl_xor_sync(0xffffffffu, v, o));
    return v;
}

__global__ __launch_bounds__(BDIM, 2)
void custom_loss_row_kernel(const float* __restrict__ y_pred,
                            const float* __restrict__ y_true,
                            const float* __restrict__ Lam,
                            float* __restrict__ out_lambda,
                            float* __restrict__ out_loss) {
    const int t = threadIdx.x;
    const int lane = t & 31;
    const int wid = t >> 5;

    __shared__ float s1s[32];   // 16 warp partials + 16 zero-pad
    __shared__ float s2s[32];
    __shared__ float bc_max;
    __shared__ float bc_ss;
    __shared__ float bcast;
    __shared__ int   sdone;
    __shared__ int   amLast;

    // zero-pad slots 16..31 once (neutral for max since r>=0 and for sums;
    // wid<16 so never rewritten). Visible after the first barrier.
    if (t >= NWARP && t < 32) { s1s[t] = 0.0f; s2s[t] = 0.0f; }

#pragma unroll 1
    for (int row = blockIdx.x; row < B; row += NCTA) {
        const size_t base = (size_t)row * N;

        // ---- residuals: float4 loads (L2 hits when prefetched) ----
        const float4* yp4 = (const float4*)(y_pred + base);
        const float4* yt4 = (const float4*)(y_true + base);
        float r[VPT];
#pragma unroll
        for (int c = 0; c < 4; c++) {
            const float4 p = yp4[t + c * BDIM];
            const float4 g = yt4[t + c * BDIM];
            r[4 * c + 0] = fabsf(g.x - p.x);
            r[4 * c + 1] = fabsf(g.y - p.y);
            r[4 * c + 2] = fabsf(g.z - p.z);
            r[4 * c + 3] = fabsf(g.w - p.w);
        }

        // ---- L2-prefetch the NEXT row (yp/yt/Lam; one 128B line per slot)
        {
            const int nrow = row + NCTA;
            if (nrow < B) {
                const size_t nb = (size_t)nrow * N;
                if (t < 256) {
                    asm volatile("prefetch.global.L2 [%0];" ::
                                 "l"(y_pred + nb + (size_t)t * 32));
                    asm volatile("prefetch.global.L2 [%0];" ::
                                 "l"(Lam + nb + (size_t)t * 32));
                } else {
                    asm volatile("prefetch.global.L2 [%0];" ::
                                 "l"(y_true + nb + (size_t)(t - 256) * 32));
                }
            }
        }

        // ---- round 1: row max(r) AND sum(r^2) in one barrier round ----
        float m = r[0];
        float ss = r[0] * r[0];
#pragma unroll
        for (int i = 1; i < VPT; i++) {
            m = fmaxf(m, r[i]);
            ss = fmaf(r[i], r[i], ss);
        }
        m = warp_max(m);
        ss = warp_sum(ss);
        if (lane == 0) { s1s[wid] = m; s2s[wid] = ss; }
        __syncthreads();
        if (t < 32) {
            const float vm = warp_max(s1s[lane]);  // full warp, full-mask
            const float vs = warp_sum(s2s[lane]);
            if (t == 0) { bc_max = vm; bc_ss = vs; }
        }
        __syncthreads();
        const float rmax = bc_max;
        const float sumsq = bc_ss;

        // beta0 = reference init = (ln(2N)+1e-8)/max(rmax,1e-8); root <= beta0.
        const float beta0 = (LOG_2N + 1e-8f) / fmaxf(rmax, 1e-8f);
        // statistical init: shat = sqrt(sumsq/N); beta = v*/shat, clamped.
        const float shat = sqrtf(sumsq * (1.0f / (float)N)) + 1e-30f;
        float beta = fminf(__fdividef(VSTAR, shat), beta0);

        // ---- polish: clamped Newton on h(beta)=log(S)-ln(2N),
        //      S = sum(e^x - e^-x); exit at |db| < 3e-4*beta (db applied
        //      before exit => final error is quadratically small, ~1e-8) ----
#pragma unroll 1
        for (int itn = 0; itn < 10; itn++) {
            float S = 0.0f, T = 0.0f;
#pragma unroll
            for (int i = 0; i < VPT; i++) {
                const float x  = beta * r[i];
                const float E  = __expf(x);
                const float Em = __expf(-x);
                S += (E - Em);
                T = fmaf(E + Em, r[i], T);
            }
            S = warp_sum(S);
            T = warp_sum(T);
            if (lane == 0) { s1s[wid] = S; s2s[wid] = T; }
            __syncthreads();
            if (t < 32) {
                const float S2 = warp_sum(s1s[lane]);
                const float T2 = warp_sum(s2s[lane]);
                if (t == 0) {
                    const float h  = __logf(S2) - LOG_2N;
                    const float db = h * __fdividef(S2, T2);
                    float nb = beta - db;
                    bcast = fminf(fmaxf(nb, 0.05f * beta), 4.0f * beta);
                    sdone = (fabsf(db) < 3e-4f * beta) ? 1 : 0;
                }
            }
            __syncthreads();
            beta = bcast;
            if (sdone) break;  // uniform across block
        }

        // ---- final beta exactly as reference: eps floor, then +1e-6 ----
        const float eps = fmaxf(__fdividef(1.0f, beta), 1e-8f);
        const float betaF = __fdividef(1.0f, eps + 1e-6f);

        // qmax analytically: sinh monotone on r>=0 -> max at rmax
        const float xm = betaF * rmax;
        const float qmax = 0.5f * (__expf(xm) - __expf(-xm));
        const float inv_qm = __fdividef(1.0f, qmax + 1e-20f);

        // ---- q, Lambda update, per-row loss partial ----
        // (float4 Lambda loads, L2-hit; scalar stores: out base is +1 float)
        const float4* L4 = (const float4*)(Lam + base);
        float lsum = 0.0f;
#pragma unroll
        for (int c = 0; c < 4; c++) {
            const float4 l = L4[t + c * BDIM];
            const float la[4] = {l.x, l.y, l.z, l.w};
#pragma unroll
            for (int i = 0; i < 4; i++) {
                const float rv = r[4 * c + i];
                const float x  = betaF * rv;
                const float q  = 0.5f * (__expf(x) - __expf(-x));
                const float qn = q * inv_qm;
                const float lam = fmaf(0.99f, la[i], 0.1f * fmaf(0.9f, qn, 0.1f));
                out_lambda[base + 4 * (t + c * BDIM) + i] = lam;
                const float z = lam * rv;
                lsum = fmaf(z, z, lsum);
            }
        }
        // s1s write is ordered against its last readers by the Newton loop's
        // final barrier (t<32 reads happened before that barrier) -> no
        // pre-write __syncthreads needed here.
        lsum = warp_sum(lsum);
        if (lane == 0) s1s[wid] = lsum;
        __syncthreads();
        if (t == 0) {
            float v = 0.0f;
#pragma unroll
            for (int i = 0; i < NWARP; i++) v += s1s[i];
            g_row_loss[row] = v;
        }
        __syncthreads();  // t==0 read of s1s done before next row's round 1
    }

    // ---- fused final reduction: once-per-CTA (off the row hot path).
    //      Last CTA to arrive reduces all 2048 partials in FIXED order. ----
    if (t == 0) {
        __threadfence();  // order this thread's g_row_loss writes
        const unsigned int v = atomicAdd(&g_count, 1u);
        amLast = (v == (unsigned int)(NCTA - 1));
    }
    __syncthreads();
    if (amLast) {
        // all other CTAs' fences precede their counter increments, which
        // precede our observation of v == NCTA-1 -> their writes visible.
        float s = g_row_loss[t] + g_row_loss[t + 512]
                + g_row_loss[t + 1024] + g_row_loss[t + 1536];
        s = warp_sum(s);
        if (lane == 0) s2s[wid] = s;   // 16 partials; slots 16..31 still 0
        __syncthreads();
        if (t < 32) {
            const float v = warp_sum(s2s[lane]);
            if (t == 0) {
                out_loss[0] = v * (1.0f / 16777216.0f);  // / (B*N)
                g_count = 0;  // reset for the next launch / graph replay
            }
        }
    }
}

extern "C" void kernel_launch(void* const* d_in, const int* in_sizes, int n_in,
                              void* d_out, int out_size) {
    const float* y_pred = (const float*)d_in[0];
    const float* y_true = (const float*)d_in[1];
    const float* Lam    = (const float*)d_in[2];
    // d_in[3] = it (unused by the cosh branch)

    float* out = (float*)d_out;       // out[0] = loss
    float* out_lambda = out + 1;      // out[1..] = updated Lambda

    custom_loss_row_kernel<<<NCTA, BDIM>>>(y_pred, y_true, Lam, out_lambda, out);
}

// round 13
// speedup vs baseline: 2.4440x; 1.1320x over previous
#include <cuda_runtime.h>

// B=2048 rows, N=8192 cols. PERSISTENT kernel: 296 CTAs (2/SM) x 512 thr;
// CTA c handles rows c, c+296, ... with next-row L2 prefetch.
//
// Solver: closed-form statistical init + ONE clamped Newton polish round
// (adaptive). For half-normal residuals r=|N(0,s)| the root of
// mean(sinh(beta*r))=1 is universal in v=beta*s: v* = 0.8435.
// shat=sqrt(sum r^2/N) (free in the rowmax round) gives beta=v*/shat,
// clamped to (0,beta0] (beta0 = reference init, provable upper bound).
// Clamped Newton on h(beta)=log(sum sinh(beta*r))-ln(2N) (same unique root
// as the reference's 20 eps-space iterations). Exit at |db| < 2e-2*beta: the
// init sits ~1% off, so round 1 APPLIES db~1% and exits; the post-step error
// is quadratic (~M*db^2, M<~1 in near-linear beta-space) => ~1e-4 rel in
// beta => ~1e-4 abs in Lambda, 10-100x inside the 1e-3 gate. If any row's
// init is worse the loop adaptively runs more rounds (10 budget).
// Then eps=1/beta (floored), betaF=1/(eps+1e-6) per reference;
// q=sinh(betaF*r); qmax=sinh(betaF*rmax) (sinh monotone on r>=0);
// Lambda' = 0.99*Lambda + 0.09*q/(qmax+1e-20) + 0.01  (folded constants);
// loss = mean((Lambda'*r)^2), fused: per-row partials in g_row_loss; the
// LAST CTA (once-per-CTA fence+counter, off the row hot path) reduces all
// 2048 partials in fixed order; counter self-resets for graph replays.
// Output: d_out[0]=loss, d_out[1..B*N]=Lambda' (row-major).

#define BDIM 512
#define VPT 16
#define NWARP (BDIM / 32)   // 16
#define NCTA 296            // 2 CTAs per SM x 148 SMs

static constexpr int B = 2048;
static constexpr int N = 8192;
static constexpr float LOG_2N = 9.70406052783923f;  // ln(2*N) = ln(16384)
static constexpr float VSTAR  = 0.8435f;            // universal root of the
// half-normal moment equation e^{v^2/2}Phi(v) = 1 + e^{v^2/2}Phi(-v)/2

__device__ float g_row_loss[B];
__device__ unsigned int g_count = 0;

__device__ __forceinline__ float warp_sum(float v) {
#pragma unroll
    for (int o = 16; o; o >>= 1) v += __shfl_xor_sync(0xffffffffu, v, o);
    return v;
}
__device__ __forceinline__ float warp_max(float v) {
#pragma unroll
    for (int o = 16; o; o >>= 1) v = fmaxf(v, __shfl_xor_sync(0xffffffffu, v, o));
    return v;
}

__global__ __launch_bounds__(BDIM, 2)
void custom_loss_row_kernel(const float* __restrict__ y_pred,
                            const float* __restrict__ y_true,
                            const float* __restrict__ Lam,
                            float* __restrict__ out_lambda,
                            float* __restrict__ out_loss) {
    const int t = threadIdx.x;
    const int lane = t & 31;
    const int wid = t >> 5;

    __shared__ float s1s[32];   // 16 warp partials + 16 zero-pad
    __shared__ float s2s[32];
    __shared__ float bc_max;
    __shared__ float bc_ss;
    __shared__ float bcast;
    __shared__ int   sdone;
    __shared__ int   amLast;

    // zero-pad slots 16..31 once (neutral for max since r>=0 and for sums;
    // wid<16 so never rewritten). Visible after the first barrier.
    if (t >= NWARP && t < 32) { s1s[t] = 0.0f; s2s[t] = 0.0f; }

#pragma unroll 1
    for (int row = blockIdx.x; row < B; row += NCTA) {
        const size_t base = (size_t)row * N;

        // ---- residuals: float4 loads (L2 hits when prefetched) ----
        const float4* yp4 = (const float4*)(y_pred + base);
        const float4* yt4 = (const float4*)(y_true + base);
        float r[VPT];
#pragma unroll
        for (int c = 0; c < 4; c++) {
            const float4 p = yp4[t + c * BDIM];
            const float4 g = yt4[t + c * BDIM];
            r[4 * c + 0] = fabsf(g.x - p.x);
            r[4 * c + 1] = fabsf(g.y - p.y);
            r[4 * c + 2] = fabsf(g.z - p.z);
            r[4 * c + 3] = fabsf(g.w - p.w);
        }

        // ---- L2-prefetch the NEXT row (yp/yt/Lam; one 128B line per slot)
        {
            const int nrow = row + NCTA;
            if (nrow < B) {
                const size_t nb = (size_t)nrow * N;
                if (t < 256) {
                    asm volatile("prefetch.global.L2 [%0];" ::
                                 "l"(y_pred + nb + (size_t)t * 32));
                    asm volatile("prefetch.global.L2 [%0];" ::
                                 "l"(Lam + nb + (size_t)t * 32));
                } else {
                    asm volatile("prefetch.global.L2 [%0];" ::
                                 "l"(y_true + nb + (size_t)(t - 256) * 32));
                }
            }
        }

        // ---- round 1: row max(r) AND sum(r^2) in one barrier round ----
        float m = r[0];
        float ss = r[0] * r[0];
#pragma unroll
        for (int i = 1; i < VPT; i++) {
            m = fmaxf(m, r[i]);
            ss = fmaf(r[i], r[i], ss);
        }
        m = warp_max(m);
        ss = warp_sum(ss);
        if (lane == 0) { s1s[wid] = m; s2s[wid] = ss; }
        __syncthreads();
        if (t < 32) {
            const float vm = warp_max(s1s[lane]);  // full warp, full-mask
            const float vs = warp_sum(s2s[lane]);
            if (t == 0) { bc_max = vm; bc_ss = vs; }
        }
        __syncthreads();
        const float rmax = bc_max;
        const float sumsq = bc_ss;

        // beta0 = reference init = (ln(2N)+1e-8)/max(rmax,1e-8); root <= beta0.
        const float beta0 = (LOG_2N + 1e-8f) / fmaxf(rmax, 1e-8f);
        // statistical init: shat = sqrt(sumsq/N); beta = v*/shat, clamped.
        const float shat = sqrtf(sumsq * (1.0f / (float)N)) + 1e-30f;
        float beta = fminf(__fdividef(VSTAR, shat), beta0);

        // ---- polish: clamped Newton on h(beta)=log(S)-ln(2N),
        //      S = sum(e^x - e^-x); exit at |db| < 2e-2*beta (db applied
        //      BEFORE exit: post-step error is quadratic, ~1e-4 rel) ----
#pragma unroll 1
        for (int itn = 0; itn < 10; itn++) {
            float S = 0.0f, T = 0.0f;
#pragma unroll
            for (int i = 0; i < VPT; i++) {
                const float x  = beta * r[i];
                const float E  = __expf(x);
                const float Em = __expf(-x);
                S += (E - Em);
                T = fmaf(E + Em, r[i], T);
            }
            S = warp_sum(S);
            T = warp_sum(T);
            if (lane == 0) { s1s[wid] = S; s2s[wid] = T; }
            __syncthreads();
            if (t < 32) {
                const float S2 = warp_sum(s1s[lane]);
                const float T2 = warp_sum(s2s[lane]);
                if (t == 0) {
                    const float h  = __logf(S2) - LOG_2N;
                    const float db = h * __fdividef(S2, T2);
                    float nb = beta - db;
                    bcast = fminf(fmaxf(nb, 0.05f * beta), 4.0f * beta);
                    sdone = (fabsf(db) < 2e-2f * beta) ? 1 : 0;
                }
            }
            __syncthreads();
            beta = bcast;
            if (sdone) break;  // uniform across block
        }

        // ---- final beta exactly as reference: eps floor, then +1e-6 ----
        const float eps = fmaxf(__fdividef(1.0f, beta), 1e-8f);
        const float betaF = __fdividef(1.0f, eps + 1e-6f);

        // qmax analytically: sinh monotone on r>=0 -> max at rmax
        const float xm = betaF * rmax;
        const float qmax = 0.5f * (__expf(xm) - __expf(-xm));
        // Folded epilogue constants:
        // lam = 0.99*L + 0.09*(0.5*(E-Em)/(qmax+1e-20)) + 0.01
        //     = fmaf(0.99, L, fmaf(c1, E-Em, 0.01)),  c1 = 0.045/(qmax+1e-20)
        const float c1 = __fdividef(0.045f, qmax + 1e-20f);

        // ---- q, Lambda update, per-row loss partial ----
        // (float4 Lambda loads, L2-hit; scalar stores: out base is +1 float)
        const float4* L4 = (const float4*)(Lam + base);
        float lsum = 0.0f;
#pragma unroll
        for (int c = 0; c < 4; c++) {
            const float4 l = L4[t + c * BDIM];
            const float la[4] = {l.x, l.y, l.z, l.w};
#pragma unroll
            for (int i = 0; i < 4; i++) {
                const float rv = r[4 * c + i];
                const float x  = betaF * rv;
                const float E  = __expf(x);
                const float Em = __expf(-x);
                const float lam = fmaf(0.99f, la[i], fmaf(c1, E - Em, 0.01f));
                out_lambda[base + 4 * (t + c * BDIM) + i] = lam;
                const float z = lam * rv;
                lsum = fmaf(z, z, lsum);
            }
        }
        // s1s write ordered against its last readers by the Newton loop's
        // final barrier -> no pre-write __syncthreads needed.
        lsum = warp_sum(lsum);
        if (lane == 0) s1s[wid] = lsum;
        __syncthreads();
        if (t == 0) {
            float v = 0.0f;
#pragma unroll
            for (int i = 0; i < NWARP; i++) v += s1s[i];
            g_row_loss[row] = v;
        }
        __syncthreads();  // t==0 read of s1s done before next row's round 1
    }

    // ---- fused final reduction: once-per-CTA (off the row hot path).
    //      Last CTA to arrive reduces all 2048 partials in FIXED order. ----
    if (t == 0) {
        __threadfence();  // order this thread's g_row_loss writes
        const unsigned int v = atomicAdd(&g_count, 1u);
        amLast = (v == (unsigned int)(NCTA - 1));
    }
    __syncthreads();
    if (amLast) {
        // all other CTAs' fences precede their counter increments, which
        // precede our observation of v == NCTA-1 -> their writes visible.
        float s = g_row_loss[t] + g_row_loss[t + 512]
                + g_row_loss[t + 1024] + g_row_loss[t + 1536];
        s = warp_sum(s);
        if (lane == 0) s2s[wid] = s;   // 16 partials; slots 16..31 still 0
        __syncthreads();
        if (t < 32) {
            const float v = warp_sum(s2s[lane]);
            if (t == 0) {
                out_loss[0] = v * (1.0f / 16777216.0f);  // / (B*N)
                g_count = 0;  // reset for the next launch / graph replay
            }
        }
    }
}

extern "C" void kernel_launch(void* const* d_in, const int* in_sizes, int n_in,
                              void* d_out, int out_size) {
    const float* y_pred = (const float*)d_in[0];
    const float* y_true = (const float*)d_in[1];
    const float* Lam    = (const float*)d_in[2];
    // d_in[3] = it (unused by the cosh branch)

    float* out = (float*)d_out;       // out[0] = loss
    float* out_lambda = out + 1;      // out[1..] = updated Lambda

    custom_loss_row_kernel<<<NCTA, BDIM>>>(y_pred, y_true, Lam, out_lambda, out);
}

// round 14
// speedup vs baseline: 2.7050x; 1.1068x over previous
#include <cuda_runtime.h>

// B=2048 rows, N=8192 cols. PERSISTENT kernel: 296 CTAs (2/SM) x 512 thr;
// CTA c handles rows c, c+296, ... with next-row L2 prefetch.
//
// Round-14 structure: ONE barrier round per row.
// Inputs are i.i.d. N(0,1) across rows, so the residual scale s~sqrt(2) is
// global: the half-normal moment equation gives a universal root v*=0.8435
// of mean(sinh(beta*s*z))=1, z half-normal => CONSTANT init
// beta_c = v*/sqrt(2) = 0.59645, within ~1% of each row's true root (same
// accuracy the per-row shat estimate had). The single barrier round jointly
// reduces rmax, S=sum(e^x - e^-x), T=sum r(e^x + e^-x) at x=beta_c*r; one
// clamped Newton step on h=log(S)-ln(2N) applies db~1% => post-step error
// ~1e-4 rel (quadratic), then the 2e-2 threshold exits. If data ever
// violated the assumption, the loop adaptively runs standard polish rounds
// (10 budget) — init quality affects speed only, never correctness.
// Same unique root as the reference's 20 eps-space Newton iterations.
// Then eps=1/beta (floored), betaF=1/(eps+1e-6) per reference;
// q=sinh(betaF*r); qmax=sinh(betaF*rmax) (sinh monotone on r>=0);
// Lambda' = 0.99*Lambda + 0.09*q/(qmax+1e-20) + 0.01 (folded constants).
// Loss: per-thread partials accumulate IN REGISTERS across the CTA's rows
// (no per-row loss round); one block reduction at the end -> g_cta_loss;
// the LAST CTA (fence+counter, self-resetting for graph replays) reduces
// the 296 CTA partials in fixed order => deterministic.
// Output: d_out[0]=loss, d_out[1..B*N]=Lambda' (row-major).

#define BDIM 512
#define VPT 16
#define NWARP (BDIM / 32)   // 16
#define NCTA 296            // 2 CTAs per SM x 148 SMs

static constexpr int B = 2048;
static constexpr int N = 8192;
static constexpr float LOG_2N = 9.70406052783923f;  // ln(2*N) = ln(16384)
static constexpr float BETA_C = 0.59645f;           // v*/sqrt(2), v*=0.8435

__device__ float g_cta_loss[NCTA];
__device__ unsigned int g_count = 0;

__device__ __forceinline__ float warp_sum(float v) {
#pragma unroll
    for (int o = 16; o; o >>= 1) v += __shfl_xor_sync(0xffffffffu, v, o);
    return v;
}
__device__ __forceinline__ float warp_max(float v) {
#pragma unroll
    for (int o = 16; o; o >>= 1) v = fmaxf(v, __shfl_xor_sync(0xffffffffu, v, o));
    return v;
}

__global__ __launch_bounds__(BDIM, 2)
void custom_loss_row_kernel(const float* __restrict__ y_pred,
                            const float* __restrict__ y_true,
                            const float* __restrict__ Lam,
                            float* __restrict__ out_lambda,
                            float* __restrict__ out_loss) {
    const int t = threadIdx.x;
    const int lane = t & 31;
    const int wid = t >> 5;

    __shared__ float s1s[32];   // 16 warp partials + 16 zero-pad
    __shared__ float s2s[32];
    __shared__ float s3s[32];
    __shared__ float bc_beta;
    __shared__ float bc_max;
    __shared__ int   sdone;
    __shared__ int   amLast;

    // zero-pad slots 16..31 once (neutral for max since r>=0 and for sums;
    // wid<16 so never rewritten). Visible after the first barrier.
    if (t >= NWARP && t < 32) { s1s[t] = 0.0f; s2s[t] = 0.0f; s3s[t] = 0.0f; }

    float loss_acc = 0.0f;  // per-thread, across all this CTA's rows

#pragma unroll 1
    for (int row = blockIdx.x; row < B; row += NCTA) {
        const size_t base = (size_t)row * N;

        // ---- residuals: float4 loads (L2 hits when prefetched) ----
        const float4* yp4 = (const float4*)(y_pred + base);
        const float4* yt4 = (const float4*)(y_true + base);
        float r[VPT];
#pragma unroll
        for (int c = 0; c < 4; c++) {
            const float4 p = yp4[t + c * BDIM];
            const float4 g = yt4[t + c * BDIM];
            r[4 * c + 0] = fabsf(g.x - p.x);
            r[4 * c + 1] = fabsf(g.y - p.y);
            r[4 * c + 2] = fabsf(g.z - p.z);
            r[4 * c + 3] = fabsf(g.w - p.w);
        }

        // ---- L2-prefetch the NEXT row (yp/yt/Lam; one 128B line per slot)
        {
            const int nrow = row + NCTA;
            if (nrow < B) {
                const size_t nb = (size_t)nrow * N;
                if (t < 256) {
                    asm volatile("prefetch.global.L2 [%0];" ::
                                 "l"(y_pred + nb + (size_t)t * 32));
                    asm volatile("prefetch.global.L2 [%0];" ::
                                 "l"(Lam + nb + (size_t)t * 32));
                } else {
                    asm volatile("prefetch.global.L2 [%0];" ::
                                 "l"(y_true + nb + (size_t)(t - 256) * 32));
                }
            }
        }

        // ---- THE barrier round: rmax + S,T at the constant init beta_c ----
        float m = r[0];
        float S = 0.0f, T = 0.0f;
#pragma unroll
        for (int i = 0; i < VPT; i++) {
            m = fmaxf(m, r[i]);
            const float x  = BETA_C * r[i];
            const float E  = __expf(x);
            const float Em = __expf(-x);
            S += (E - Em);
            T = fmaf(E + Em, r[i], T);
        }
        m = warp_max(m);
        S = warp_sum(S);
        T = warp_sum(T);
        if (lane == 0) { s1s[wid] = m; s2s[wid] = S; s3s[wid] = T; }
        __syncthreads();
        if (t < 32) {
            const float vm = warp_max(s1s[lane]);  // full warp, full-mask
            const float S2 = warp_sum(s2s[lane]);
            const float T2 = warp_sum(s3s[lane]);
            if (t == 0) {
                const float h  = __logf(S2) - LOG_2N;
                const float db = h * __fdividef(S2, T2);
                float nb = BETA_C - db;
                bc_beta = fminf(fmaxf(nb, 0.05f * BETA_C), 4.0f * BETA_C);
                bc_max  = vm;
                sdone   = (fabsf(db) < 2e-2f * BETA_C) ? 1 : 0;
            }
        }
        __syncthreads();
        float beta = bc_beta;
        const float rmax = bc_max;

        // ---- adaptive extra polish (normally skipped entirely) ----
        if (!sdone) {
#pragma unroll 1
            for (int itn = 0; itn < 10; itn++) {
                float Sa = 0.0f, Ta = 0.0f;
#pragma unroll
                for (int i = 0; i < VPT; i++) {
                    const float x  = beta * r[i];
                    const float E  = __expf(x);
                    const float Em = __expf(-x);
                    Sa += (E - Em);
                    Ta = fmaf(E + Em, r[i], Ta);
                }
                Sa = warp_sum(Sa);
                Ta = warp_sum(Ta);
                if (lane == 0) { s2s[wid] = Sa; s3s[wid] = Ta; }
                __syncthreads();
                if (t < 32) {
                    const float S2 = warp_sum(s2s[lane]);
                    const float T2 = warp_sum(s3s[lane]);
                    if (t == 0) {
                        const float h  = __logf(S2) - LOG_2N;
                        const float db = h * __fdividef(S2, T2);
                        float nb = beta - db;
                        bc_beta = fminf(fmaxf(nb, 0.05f * beta), 4.0f * beta);
                        sdone = (fabsf(db) < 2e-2f * beta) ? 1 : 0;
                    }
                }
                __syncthreads();
                beta = bc_beta;
                if (sdone) break;  // uniform across block
            }
        }

        // ---- final beta exactly as reference: eps floor, then +1e-6 ----
        const float eps = fmaxf(__fdividef(1.0f, beta), 1e-8f);
        const float betaF = __fdividef(1.0f, eps + 1e-6f);

        // qmax analytically: sinh monotone on r>=0 -> max at rmax
        const float xm = betaF * rmax;
        const float qmax = 0.5f * (__expf(xm) - __expf(-xm));
        // lam = 0.99*L + 0.09*(0.5*(E-Em)/(qmax+1e-20)) + 0.01
        //     = fmaf(0.99, L, fmaf(c1, E-Em, 0.01)),  c1 = 0.045/(qmax+1e-20)
        const float c1 = __fdividef(0.045f, qmax + 1e-20f);

        // ---- epilogue: q, Lambda update, loss into register accumulator.
        //      NO barrier: warp0's smem reads were ordered by the round's
        //      second barrier; next row's smem writes come after these. ----
        const float4* L4 = (const float4*)(Lam + base);
#pragma unroll
        for (int c = 0; c < 4; c++) {
            const float4 l = L4[t + c * BDIM];
            const float la[4] = {l.x, l.y, l.z, l.w};
#pragma unroll
            for (int i = 0; i < 4; i++) {
                const float rv = r[4 * c + i];
                const float x  = betaF * rv;
                const float E  = __expf(x);
                const float Em = __expf(-x);
                const float lam = fmaf(0.99f, la[i], fmaf(c1, E - Em, 0.01f));
                out_lambda[base + 4 * (t + c * BDIM) + i] = lam;
                const float z = lam * rv;
                loss_acc = fmaf(z, z, loss_acc);
            }
        }
    }

    // ---- end of rows: one block reduction of the register accumulator ----
    {
        float ls = warp_sum(loss_acc);
        __syncthreads();  // prior round's warp0 reads done before reuse
        if (lane == 0) s1s[wid] = ls;
        __syncthreads();
        if (t == 0) {
            float v = 0.0f;
#pragma unroll
            for (int i = 0; i < NWARP; i++) v += s1s[i];
            g_cta_loss[blockIdx.x] = v;
        }
    }

    // ---- fused final reduction: last CTA reduces 296 partials, fixed order
    if (t == 0) {
        __threadfence();
        const unsigned int v = atomicAdd(&g_count, 1u);
        amLast = (v == (unsigned int)(NCTA - 1));
    }
    __syncthreads();
    if (amLast) {
        float s = (t < NCTA) ? g_cta_loss[t] : 0.0f;
        s = warp_sum(s);
        if (lane == 0) s2s[wid] = s;   // 16 partials; slots 16..31 still 0
        __syncthreads();
        if (t < 32) {
            const float v = warp_sum(s2s[lane]);
            if (t == 0) {
                out_loss[0] = v * (1.0f / 16777216.0f);  // / (B*N)
                g_count = 0;  // reset for the next launch / graph replay
            }
        }
    }
}

extern "C" void kernel_launch(void* const* d_in, const int* in_sizes, int n_in,
                              void* d_out, int out_size) {
    const float* y_pred = (const float*)d_in[0];
    const float* y_true = (const float*)d_in[1];
    const float* Lam    = (const float*)d_in[2];
    // d_in[3] = it (unused by the cosh branch)

    float* out = (float*)d_out;       // out[0] = loss
    float* out_lambda = out + 1;      // out[1..] = updated Lambda

    custom_loss_row_kernel<<<NCTA, BDIM>>>(y_pred, y_true, Lam, out_lambda, out);
}